// round 2
// baseline (speedup 1.0000x reference)
#include <cuda_runtime.h>
#include <math.h>

#define TT 200
#define BB 32
#define EE 300
#define HH 1000
#define KTAGS 9
#define G4 4000   // 4*HH

// ---------------- scratch (device globals; no runtime allocation) ----------------
__device__ float g_xg[(size_t)TT * BB * G4];   // 102.4 MB  input-gate preactivations
__device__ float g_hs[(size_t)TT * BB * HH];   // 25.6 MB   hidden states (also h double buffer)
__device__ float g_cbuf[2 * BB * HH];          // cell state double buffer
__device__ float g_zero[BB * HH];              // never written -> stays zero (module load zero-init)
__device__ float g_em[TT * BB * KTAGS];        // emissions (log_softmax over batch)

// =====================================================================
// K1: xg[t,b,g] = sum_e embed_w[x[t,b],e] * W_ih[g,e] + b_ih[g] + b_hh[g]
// grid (63, 200) block 256.  Block tile: 32 b x 64 g, K tiled by 20.
// =====================================================================
__global__ void __launch_bounds__(256) k1_xg(
    const int* __restrict__ x, const float* __restrict__ embed_w,
    const float* __restrict__ W_ih, const float* __restrict__ b_ih,
    const float* __restrict__ b_hh)
{
    __shared__ __align__(16) float As[32 * 28];  // embeds tile, row stride 28 (conflict-free f4)
    __shared__ __align__(16) float Bs[64 * 28];  // W_ih tile

    const int t   = blockIdx.y;
    const int n0  = blockIdx.x * 64;
    const int tid = threadIdx.x;
    const int b   = tid & 31;
    const int nl  = tid >> 5;    // 0..7

    float acc[8];
#pragma unroll
    for (int i = 0; i < 8; i++) acc[i] = 0.f;

    for (int k0 = 0; k0 < EE; k0 += 20) {
        __syncthreads();
        for (int i = tid; i < 480; i += 256) {
            const int ko = (i % 5) * 4;
            if (i < 160) {
                const int r   = i / 5;
                const int tok = x[t * BB + r];
                *reinterpret_cast<float4*>(&As[r * 28 + ko]) =
                    *reinterpret_cast<const float4*>(embed_w + (size_t)tok * EE + k0 + ko);
            } else {
                const int r   = (i - 160) / 5;
                const int row = n0 + r;
                float4 v = make_float4(0.f, 0.f, 0.f, 0.f);
                if (row < G4)
                    v = *reinterpret_cast<const float4*>(W_ih + (size_t)row * EE + k0 + ko);
                *reinterpret_cast<float4*>(&Bs[r * 28 + ko]) = v;
            }
        }
        __syncthreads();
#pragma unroll
        for (int kk = 0; kk < 20; kk += 4) {
            const float4 a4 = *reinterpret_cast<const float4*>(&As[b * 28 + kk]);
#pragma unroll
            for (int i = 0; i < 8; i++) {
                const float4 w4 = *reinterpret_cast<const float4*>(&Bs[(nl * 8 + i) * 28 + kk]);
                acc[i] += a4.x * w4.x + a4.y * w4.y + a4.z * w4.z + a4.w * w4.w;
            }
        }
    }

#pragma unroll
    for (int i = 0; i < 8; i++) {
        const int n = n0 + nl * 8 + i;
        if (n < G4)
            g_xg[(size_t)t * (BB * G4) + b * G4 + n] = acc[i] + b_ih[n] + b_hh[n];
    }
}

// =====================================================================
// K2: one LSTM step. grid 125, block 256.
// Block handles all 32 b, 8 hidden indices j, ALL 4 gates for those j
// (rows {j, 1000+j, 2000+j, 3000+j} of W_hh) so gates fuse in-kernel.
// thread = (jl = tid>>5 in 0..7, b = tid&31); 4 accumulators (one per gate).
// =====================================================================
__global__ void __launch_bounds__(256) k2_step(int t, const float* __restrict__ W_hh)
{
    __shared__ __align__(16) float hsh[32 * 28];
    __shared__ __align__(16) float wsh[32 * 28];

    const float* __restrict__ xg_t = g_xg + (size_t)t * (BB * G4);
    const float* __restrict__ h_in = (t == 0) ? g_zero : (g_hs + (size_t)(t - 1) * (BB * HH));
    const float* __restrict__ c_in = (t == 0) ? g_zero : (g_cbuf + ((t - 1) & 1) * (BB * HH));
    float* __restrict__ c_out = g_cbuf + (t & 1) * (BB * HH);
    float* __restrict__ h_out = g_hs + (size_t)t * (BB * HH);

    const int tid = threadIdx.x;
    const int b   = tid & 31;
    const int jl  = tid >> 5;            // 0..7
    const int j0  = blockIdx.x * 8;
    const int j   = j0 + jl;

    float acc[4] = {0.f, 0.f, 0.f, 0.f};

    for (int k0 = 0; k0 < HH; k0 += 20) {
        __syncthreads();
        for (int i = tid; i < 320; i += 256) {
            const int ko = (i % 5) * 4;
            if (i < 160) {
                const int r = i / 5;
                *reinterpret_cast<float4*>(&hsh[r * 28 + ko]) =
                    *reinterpret_cast<const float4*>(h_in + r * HH + k0 + ko);
            } else {
                const int s = (i - 160) / 5;          // 0..31 : gate*8 + jj
                const int g = s >> 3, jj = s & 7;
                *reinterpret_cast<float4*>(&wsh[s * 28 + ko]) =
                    *reinterpret_cast<const float4*>(W_hh + (size_t)(g * HH + j0 + jj) * HH + k0 + ko);
            }
        }
        __syncthreads();
#pragma unroll
        for (int kk = 0; kk < 20; kk += 4) {
            const float4 h4 = *reinterpret_cast<const float4*>(&hsh[b * 28 + kk]);
#pragma unroll
            for (int g = 0; g < 4; g++) {
                const float4 w4 = *reinterpret_cast<const float4*>(&wsh[(g * 8 + jl) * 28 + kk]);
                acc[g] += h4.x * w4.x + h4.y * w4.y + h4.z * w4.z + h4.w * w4.w;
            }
        }
    }

    // gates (PyTorch order i,f,g,o as row chunks of 1000)
    float pre[4];
#pragma unroll
    for (int g = 0; g < 4; g++) pre[g] = acc[g] + xg_t[b * G4 + g * HH + j];

    const float ig = 1.f / (1.f + expf(-pre[0]));
    const float fg = 1.f / (1.f + expf(-pre[1]));
    const float gg = tanhf(pre[2]);
    const float og = 1.f / (1.f + expf(-pre[3]));
    const float c  = fg * c_in[b * HH + j] + ig * gg;
    const float h  = og * tanhf(c);
    c_out[b * HH + j] = c;
    h_out[b * HH + j] = h;
}

// =====================================================================
// K3: tag_space + log_softmax over BATCH axis -> emissions.
// grid 200 (t), block 288 (warp w = tag k, lane = b).
// =====================================================================
__global__ void __launch_bounds__(288) k3_emis(
    const float* __restrict__ lin_w, const float* __restrict__ lin_b)
{
    __shared__ float hssh[32 * 101];
    __shared__ float lsh[9 * 101];

    const int t   = blockIdx.x;
    const int tid = threadIdx.x;
    const int b   = tid & 31;
    const int k   = tid >> 5;   // 0..8

    float acc = 0.f;
    for (int h0 = 0; h0 < HH; h0 += 100) {
        __syncthreads();
        for (int i = tid; i < 3200; i += 288) {
            const int r = i / 100, c = i % 100;
            hssh[r * 101 + c] = g_hs[(size_t)t * (BB * HH) + r * HH + h0 + c];
        }
        for (int i = tid; i < 900; i += 288) {
            const int r = i / 100, c = i % 100;
            lsh[r * 101 + c] = lin_w[r * HH + h0 + c];
        }
        __syncthreads();
#pragma unroll 4
        for (int c = 0; c < 100; c++)
            acc += hssh[b * 101 + c] * lsh[k * 101 + c];
    }
    acc += lin_b[k];

    // log_softmax over batch (the 32 lanes of this warp)
    float m = acc;
#pragma unroll
    for (int off = 16; off; off >>= 1)
        m = fmaxf(m, __shfl_xor_sync(0xffffffffu, m, off));
    float s = expf(acc - m);
#pragma unroll
    for (int off = 16; off; off >>= 1)
        s += __shfl_xor_sync(0xffffffffu, s, off);

    g_em[t * (BB * KTAGS) + b * KTAGS + k] = acc - m - logf(s);
}

// =====================================================================
// K4: CRF forward + numerator + final scalar. 1 block, 288 threads (b,j).
// =====================================================================
__global__ void __launch_bounds__(288) k4_crf(
    const int* __restrict__ y,
    const float* __restrict__ start_trans, const float* __restrict__ end_trans,
    const float* __restrict__ trans, float* __restrict__ out)
{
    __shared__ float tr[81];
    __shared__ float st[9], en[9];
    __shared__ float bufA[32 * 10], bufB[32 * 10];
    __shared__ int   ysh[TT * BB];
    __shared__ float nump[32 * 10];
    __shared__ float numsh[32], lzsh[32];

    const int tid = threadIdx.x;
    const int b = tid / 9, j = tid % 9;

    if (tid < 81) tr[tid] = trans[tid];
    if (tid < 9) { st[tid] = start_trans[tid]; en[tid] = end_trans[tid]; }
    for (int i = tid; i < TT * BB; i += 288) ysh[i] = y[i];
    __syncthreads();

    // alpha0
    bufA[b * 10 + j] = st[j] + g_em[b * KTAGS + j];
    __syncthreads();

    float* cur = bufA;
    float* nxt = bufB;
    for (int t = 1; t < TT; t++) {
        float m = -1e30f;
#pragma unroll
        for (int i = 0; i < 9; i++) m = fmaxf(m, cur[b * 10 + i] + tr[i * 9 + j]);
        float s = 0.f;
#pragma unroll
        for (int i = 0; i < 9; i++) s += expf(cur[b * 10 + i] + tr[i * 9 + j] - m);
        nxt[b * 10 + j] = m + logf(s) + g_em[t * (BB * KTAGS) + b * KTAGS + j];
        __syncthreads();
        float* tmp = cur; cur = nxt; nxt = tmp;
    }

    // log_z per batch (j==0 threads)
    if (j == 0) {
        float m = -1e30f;
        for (int i = 0; i < 9; i++) m = fmaxf(m, cur[b * 10 + i] + en[i]);
        float s = 0.f;
        for (int i = 0; i < 9; i++) s += expf(cur[b * 10 + i] + en[i] - m);
        lzsh[b] = m + logf(s);
    }

    // numerator: strided over t by j, then deterministic tree-ish reduce
    float part = 0.f;
    for (int t = j; t < TT; t += 9) {
        const int yt = ysh[t * BB + b];
        part += g_em[t * (BB * KTAGS) + b * KTAGS + yt];
        if (t > 0) part += tr[ysh[(t - 1) * BB + b] * 9 + yt];
    }
    if (j == 0) part += st[ysh[b]] + en[ysh[(TT - 1) * BB + b]];
    nump[b * 10 + j] = part;
    __syncthreads();

    if (j == 0) {
        float n = 0.f;
        for (int i = 0; i < 9; i++) n += nump[b * 10 + i];
        numsh[b] = n;
    }
    __syncthreads();

    if (tid == 0) {
        float tot = 0.f;
        for (int bb = 0; bb < BB; bb++) tot += numsh[bb] - lzsh[bb];
        out[0] = tot;
    }
}

// =====================================================================
extern "C" void kernel_launch(void* const* d_in, const int* in_sizes, int n_in,
                              void* d_out, int out_size)
{
    const int*   x        = (const int*)  d_in[0];
    const int*   y        = (const int*)  d_in[1];
    const float* embed_w  = (const float*)d_in[2];
    const float* W_ih     = (const float*)d_in[3];
    const float* W_hh     = (const float*)d_in[4];
    const float* b_ih     = (const float*)d_in[5];
    const float* b_hh     = (const float*)d_in[6];
    const float* lin_w    = (const float*)d_in[7];
    const float* lin_b    = (const float*)d_in[8];
    const float* start_tr = (const float*)d_in[9];
    const float* end_tr   = (const float*)d_in[10];
    const float* trans    = (const float*)d_in[11];
    float* out = (float*)d_out;

    // K1: input-gate preactivations for all timesteps
    dim3 g1(63, TT);
    k1_xg<<<g1, 256>>>(x, embed_w, W_ih, b_ih, b_hh);

    // K2: 200 sequential fused LSTM steps
    for (int t = 0; t < TT; t++)
        k2_step<<<125, 256>>>(t, W_hh);

    // K3: emissions
    k3_emis<<<TT, 288>>>(lin_w, lin_b);

    // K4: CRF + scalar output
    k4_crf<<<1, 288>>>(y, start_tr, end_tr, trans, out);
}